// round 2
// baseline (speedup 1.0000x reference)
#include <cuda_runtime.h>

#define WIDTH 512
#define HEIGHT 512
#define NPLANES 96
#define SKEW 3
#define NSTEP (WIDTH + SKEW * 31)

// Floyd-Steinberg 1-bit error diffusion, warp-per-plane anti-diagonal wavefront.
// Lane l handles row (band*32 + l), processing column c = t - 3*l at step t.
// Cross-lane err flow via shfl_up with 2 steps of slack (skew 3) so the 26-cyc
// SHFL latency is off the per-step critical path.
__global__ void __launch_bounds__(32, 1)
fs_dither_kernel(const float* __restrict__ x, float* __restrict__ out) {
    const int plane = blockIdx.x;
    const int lane = threadIdx.x & 31;

    const float* __restrict__ xp = x + (size_t)plane * (HEIGHT * WIDTH);
    float* __restrict__ op = out + (size_t)plane * (HEIGHT * WIDTH);

    __shared__ float buf[2][WIDTH];

    // Band 0 has a zero previous row.
    for (int i = lane; i < WIDTH; i += 32) buf[0][i] = 0.0f;
    __syncwarp();

    int cur = 0;
    for (int band = 0; band < HEIGHT / 32; ++band) {
        const float* prev = buf[cur];
        float* nxt = buf[cur ^ 1];
        const int row = band * 32 + lane;
        const float* __restrict__ xrow = xp + (size_t)row * WIDTH;
        float* __restrict__ orow = op + (size_t)row * WIDTH;

        // Delay line: at start of step t we need
        //   e_ur = inc(t-2), e_u = inc(t-3), e_ul = inc(t-4)
        // where inc(t) = err of row-above at column t+3 (lane 0: from prev[]).
        float r1, r2, r3, r4;
        if (lane == 0) {
            r4 = 0.0f;        // inc(-4) = prev[-1] (pad)
            r3 = prev[0];     // inc(-3)
            r2 = prev[1];     // inc(-2)
            r1 = prev[2];     // inc(-1)
        } else {
            r1 = r2 = r3 = r4 = 0.0f;   // upstream lane not yet active
        }
        float left = 0.0f;

        #pragma unroll 4
        for (int t = 0; t < NSTEP; ++t) {
            const int c = t - SKEW * lane;
            const bool active = ((unsigned)c < (unsigned)WIDTH);
            const float e_ur = r2, e_u = r3, e_ul = r4;

            // Clamped-address load so inactive lanes stay branch-free.
            int cl = c < 0 ? 0 : (c > WIDTH - 1 ? WIDTH - 1 : c);
            float xv = __ldg(xrow + cl);

            // x = clip(x,-1,1); x01 = (x+1)/2   (exact, matches reference)
            xv = fminf(fmaxf(xv, -1.0f), 1.0f);
            float x01 = __fmul_rn(__fadd_rn(xv, 1.0f), 0.5f);

            // up = (1/16*e_ul + 5/16*e_u) + 3/16*e_ur  (reference assoc order, no FMA)
            float u = __fadd_rn(__fadd_rn(__fmul_rn(0.0625f, e_ul),
                                          __fmul_rn(0.3125f, e_u)),
                                __fmul_rn(0.1875f, e_ur));
            float pre = __fadd_rn(x01, u);
            float raw = __fadd_rn(pre, __fmul_rn(0.4375f, left));
            float val = fminf(fmaxf(raw, 0.0f), 1.0f);

            // q = round-half-even(val) for val in [0,1]  <=>  raw > 0.5.
            // d = 0.5 - raw: sign is exact (Sterbenz for raw in [0.25,1];
            // sign trivially preserved outside). Tie raw==0.5 -> d=+0 -> q=0 (half-even).
            float d = __fadd_rn(0.5f, -raw);
            int smask = __float_as_int(d) >> 31;              // 0 or -1 (q mask)
            unsigned s = (unsigned)smask;
            // err = val - q, exact: val + (-1.0f if q else +0.0f); Sterbenz-exact.
            float err = __fadd_rn(val, __uint_as_float(s & 0xBF800000u));
            err = active ? err : 0.0f;   // inactive lanes feed 0 (padding) downstream

            if (active) {
                // output = 2*q - 1 in {-1,+1}
                orow[c] = __uint_as_float(0xBF800000u ^ (s & 0x80000000u));
                if (lane == 31) nxt[c] = err;   // hand off to next band
            }
            left = err;   // 0 while inactive, so first active column sees left=0

            // Cross-lane propagation (2 steps of slack before consumption).
            float sh = __shfl_up_sync(0xFFFFFFFFu, err, 1);
            if (lane == 0) {
                int pi = t + SKEW;
                sh = (pi < WIDTH) ? prev[pi] : 0.0f;
            }
            r4 = r3; r3 = r2; r2 = r1; r1 = sh;
        }
        __syncwarp();
        cur ^= 1;
    }
}

extern "C" void kernel_launch(void* const* d_in, const int* in_sizes, int n_in,
                              void* d_out, int out_size) {
    (void)in_sizes; (void)n_in; (void)out_size;
    const float* x = (const float*)d_in[0];
    float* out = (float*)d_out;
    fs_dither_kernel<<<NPLANES, 32>>>(x, out);
}

// round 3
// speedup vs baseline: 14.4454x; 14.4454x over previous
#include <cuda_runtime.h>

#define W 512
#define H 512
#define NPLANES 96
#define SKEW 3
#define NWARPS 16            // one band (32 rows) per warp, whole plane per block
#define CH 16                // columns per sync chunk
#define LAG 96               // 32 rows * SKEW: producer lead needed by consumer
#define NSTEP_PAD 608        // ceil((512 + 3*31)=605 to multiple of CH)
#define NCHUNK (NSTEP_PAD / CH)

// Floyd-Steinberg 1-bit error diffusion.
// Block = one 512x512 plane, 16 warps. Warp w owns rows [32w, 32w+32).
// Within a warp: anti-diagonal wavefront, lane l handles row 32w+l at
// column c = t - 3l (skew 3 -> 1 full step of slack over the 26-cyc SHFL).
// Across warps: band pipeline; warp w-1's lane-31 err row is handed to
// warp w through SMEM in 16-column chunks guarded by a volatile progress
// counter + __threadfence_block (release/acquire within the CTA).
__global__ void __launch_bounds__(NWARPS * 32, 1)
fs_dither_kernel(const float* __restrict__ x, float* __restrict__ out) {
    __shared__ float errbuf[NWARPS][W];
    __shared__ float zbuf[W];
    __shared__ volatile unsigned progress[NWARPS];

    const int tid = threadIdx.x;
    const int w = tid >> 5;
    const int lane = tid & 31;
    const int plane = blockIdx.x;

    const float* __restrict__ xp = x + (size_t)plane * (H * W);
    float* __restrict__ op = out + (size_t)plane * (H * W);

    for (int i = tid; i < W; i += NWARPS * 32) zbuf[i] = 0.0f;
    if (tid < NWARPS) progress[tid] = 0u;
    __syncthreads();

    const float* __restrict__ prevrow = (w == 0) ? zbuf : errbuf[w - 1];
    float* __restrict__ myrow = errbuf[w];

    const int row = w * 32 + lane;
    const float* __restrict__ xrow = xp + (size_t)row * W;
    float* __restrict__ orow = op + (size_t)row * W;

    // Delay line: at step t lane l consumes e_ur=r2, e_u=r3, e_ul=r4, which are
    // the row-above errs at columns c+1, c, c-1 (c = t - 3*lane); r1 is the
    // 3-ahead prefetch (lane 0: from prevrow[t+3], lanes>0: shfl from above).
    float r1 = 0.0f, r2 = 0.0f, r3 = 0.0f, r4 = 0.0f;
    float left = 0.0f;

    int t = 0;
    for (int k = 0; k < NCHUNK; ++k) {
        if (w != 0) {
            unsigned need = (unsigned)(t + CH + LAG);
            if (need > NSTEP_PAD) need = NSTEP_PAD;
            while (progress[w - 1] < need) { /* spin */ }
        }
        __syncwarp();
        __threadfence_block();   // acquire: producer's STS now visible

        if (k == 0 && lane == 0) {
            // prev[-1]=0 (pad), prev[0..2]; gated by the first poll (need>=112>95)
            r4 = 0.0f;
            r3 = prevrow[0];
            r2 = prevrow[1];
            r1 = prevrow[2];
        }

        #pragma unroll
        for (int i = 0; i < CH; ++i, ++t) {
            const int c = t - SKEW * lane;
            const bool active = ((unsigned)c < (unsigned)W);
            const float e_ur = r2, e_u = r3, e_ul = r4;

            // Clamped-address load keeps inactive lanes branch-free (L1-hit).
            int cl = c < 0 ? 0 : (c > W - 1 ? W - 1 : c);
            float xv = __ldg(xrow + cl);

            // x = clip(x,-1,1); x01 = (x+1)/2  (exact, matches reference)
            xv = fminf(fmaxf(xv, -1.0f), 1.0f);
            float x01 = __fmul_rn(__fadd_rn(xv, 1.0f), 0.5f);

            // up = (1/16*e_ul + 5/16*e_u) + 3/16*e_ur  (reference order, no FMA)
            float u = __fadd_rn(__fadd_rn(__fmul_rn(0.0625f, e_ul),
                                          __fmul_rn(0.3125f, e_u)),
                                __fmul_rn(0.1875f, e_ur));
            float pre = __fadd_rn(x01, u);
            float raw = __fadd_rn(pre, __fmul_rn(0.4375f, left));
            float val = fminf(fmaxf(raw, 0.0f), 1.0f);

            // q = round-half-even(val), val in [0,1]  <=>  raw > 0.5.
            // d = 0.5 - raw has exact sign (Sterbenz in [0.25,1]); tie -> q=0.
            float d = __fadd_rn(0.5f, -raw);
            unsigned s = (unsigned)(__float_as_int(d) >> 31);
            // err = val - q exactly: val + (-1.0f masked); Sterbenz-exact.
            float err = __fadd_rn(val, __uint_as_float(s & 0xBF800000u));
            err = active ? err : 0.0f;   // inactive lanes feed zero padding

            if (active) {
                // output = 2*q - 1 in {-1,+1}
                orow[c] = __uint_as_float(0xBF800000u ^ (s & 0x80000000u));
                if (lane == 31) myrow[c] = err;   // hand off to next band
            }
            left = err;

            // Cross-lane propagation (1 step of slack before consumption).
            float sh = __shfl_up_sync(0xFFFFFFFFu, err, 1);
            const int pi = t + SKEW;
            float pv = (pi < W) ? prevrow[pi] : 0.0f;  // broadcast LDS
            if (lane == 0) sh = pv;                    // SEL, no branch
            r4 = r3; r3 = r2; r2 = r1; r1 = sh;
        }

        if (lane == 31) {
            __threadfence_block();        // release: STS before counter
            progress[w] = (unsigned)t;
        }
    }
}

extern "C" void kernel_launch(void* const* d_in, const int* in_sizes, int n_in,
                              void* d_out, int out_size) {
    (void)in_sizes; (void)n_in; (void)out_size;
    const float* x = (const float*)d_in[0];
    float* out = (float*)d_out;
    fs_dither_kernel<<<NPLANES, NWARPS * 32>>>(x, out);
}